// round 1
// baseline (speedup 1.0000x reference)
#include <cuda_runtime.h>
#include <math.h>

// Problem constants
static const int NB = 16;    // batch
static const int CH = 256;   // channels (in = key = val)
static const int S  = 4096;  // spatial (64*64)
static const int NH = 8;     // heads
static const int HC = 32;    // per-head channels

// ---------------- scratch (device globals; no allocations allowed) ----------
__device__ float g_K [(size_t)NB * CH * S];
__device__ float g_Q [(size_t)NB * CH * S];
__device__ float g_V [(size_t)NB * CH * S];
__device__ float g_att[(size_t)NB * CH * S];
__device__ float g_ctx[NB * NH * HC * HC];
__device__ float g_rmax[NB * CH];
__device__ float g_rinv[NB * CH];

// ---------------------------------------------------------------------------
// Batched SGEMM: Cout[b][m][n] = sum_k A[m][k] * B[b][k][n] + bias[m] (+ Res[b][m][n])
// A: [M,K] row-major (shared across batch). B: batch-strided [K,N]. 128x128x8 tiles.
// ---------------------------------------------------------------------------
__global__ void __launch_bounds__(256) sgemm_bias(
    const float* __restrict__ A,
    const float* __restrict__ Bmat,
    const float* __restrict__ bias,
    const float* __restrict__ Res,      // nullptr if no residual
    float* __restrict__ Cout,
    int M, int N, int K)
{
    const int n0 = blockIdx.x * 128;
    const int m0 = blockIdx.y * 128;
    const size_t bOff = (size_t)blockIdx.z * K * N;
    const size_t cOff = (size_t)blockIdx.z * M * N;

    __shared__ float sA[2][8][128];
    __shared__ float sB[2][8][128];

    const int tid = threadIdx.x;
    const int tx = tid & 15;        // 0..15 -> 8 cols each
    const int ty = tid >> 4;        // 0..15 -> 8 rows each

    // A-tile load mapping: 128 rows x 8 k; thread loads one float4
    const int arow = tid >> 1;            // 0..127
    const int acol = (tid & 1) * 4;       // 0 or 4
    // B-tile load mapping: 8 k-rows x 128 cols; thread loads one float4
    const int brow = tid >> 5;            // 0..7
    const int bcol = (tid & 31) * 4;      // 0..124

    const float* Aptr = A + (size_t)(m0 + arow) * K + acol;
    const float* Bptr = Bmat + bOff + (size_t)brow * N + n0 + bcol;

    float acc[8][8];
#pragma unroll
    for (int i = 0; i < 8; ++i)
#pragma unroll
        for (int j = 0; j < 8; ++j) acc[i][j] = 0.f;

    // preload k-tile 0
    float4 a4 = *(const float4*)(Aptr);
    float4 b4 = *(const float4*)(Bptr);
    sA[0][acol + 0][arow] = a4.x;
    sA[0][acol + 1][arow] = a4.y;
    sA[0][acol + 2][arow] = a4.z;
    sA[0][acol + 3][arow] = a4.w;
    *(float4*)&sB[0][brow][bcol] = b4;
    __syncthreads();

    const int nk = K / 8;
    for (int kt = 0; kt < nk; ++kt) {
        const int cur = kt & 1;
        if (kt + 1 < nk) {
            a4 = *(const float4*)(Aptr + (kt + 1) * 8);
            b4 = *(const float4*)(Bptr + (size_t)(kt + 1) * 8 * N);
        }
#pragma unroll
        for (int kk = 0; kk < 8; ++kk) {
            float ra[8], rb[8];
            *(float4*)&ra[0] = *(float4*)&sA[cur][kk][ty * 8];
            *(float4*)&ra[4] = *(float4*)&sA[cur][kk][ty * 8 + 4];
            *(float4*)&rb[0] = *(float4*)&sB[cur][kk][tx * 8];
            *(float4*)&rb[4] = *(float4*)&sB[cur][kk][tx * 8 + 4];
#pragma unroll
            for (int i = 0; i < 8; ++i)
#pragma unroll
                for (int j = 0; j < 8; ++j)
                    acc[i][j] = fmaf(ra[i], rb[j], acc[i][j]);
        }
        if (kt + 1 < nk) {
            const int nxt = cur ^ 1;
            sA[nxt][acol + 0][arow] = a4.x;
            sA[nxt][acol + 1][arow] = a4.y;
            sA[nxt][acol + 2][arow] = a4.z;
            sA[nxt][acol + 3][arow] = a4.w;
            *(float4*)&sB[nxt][brow][bcol] = b4;
        }
        __syncthreads();
    }

    // epilogue: bias (+residual), vectorized stores
#pragma unroll
    for (int i = 0; i < 8; ++i) {
        const int m = m0 + ty * 8 + i;
        const float bvv = bias[m];
        const size_t off = cOff + (size_t)m * N + n0 + tx * 8;
        float4 o0, o1;
        o0.x = acc[i][0] + bvv; o0.y = acc[i][1] + bvv;
        o0.z = acc[i][2] + bvv; o0.w = acc[i][3] + bvv;
        o1.x = acc[i][4] + bvv; o1.y = acc[i][5] + bvv;
        o1.z = acc[i][6] + bvv; o1.w = acc[i][7] + bvv;
        if (Res) {
            float4 r0 = *(const float4*)(Res + off);
            float4 r1 = *(const float4*)(Res + off + 4);
            o0.x += r0.x; o0.y += r0.y; o0.z += r0.z; o0.w += r0.w;
            o1.x += r1.x; o1.y += r1.y; o1.z += r1.z; o1.w += r1.w;
        }
        *(float4*)(Cout + off) = o0;
        *(float4*)(Cout + off + 4) = o1;
    }
}

// ---------------------------------------------------------------------------
// Per-row softmax statistics for K: max and 1/sum(exp) over the S dimension.
// One block per row (NB*CH = 4096 rows of S=4096 elements).
// ---------------------------------------------------------------------------
__global__ void __launch_bounds__(256) row_stats(
    const float* __restrict__ Kin,
    float* __restrict__ rmax,
    float* __restrict__ rinv)
{
    const int row = blockIdx.x;
    const float* p = Kin + (size_t)row * S;
    const int tid = threadIdx.x;

    float v[16];
    float m = -3.4e38f;
#pragma unroll
    for (int e = 0; e < 16; ++e) {
        v[e] = p[tid + e * 256];
        m = fmaxf(m, v[e]);
    }
    __shared__ float red[16];
#pragma unroll
    for (int o = 16; o; o >>= 1) m = fmaxf(m, __shfl_xor_sync(0xffffffffu, m, o));
    const int warp = tid >> 5, lane = tid & 31;
    if (lane == 0) red[warp] = m;
    __syncthreads();
    float bm = red[0];
#pragma unroll
    for (int i = 1; i < 8; ++i) bm = fmaxf(bm, red[i]);

    float s = 0.f;
#pragma unroll
    for (int e = 0; e < 16; ++e) s += __expf(v[e] - bm);
#pragma unroll
    for (int o = 16; o; o >>= 1) s += __shfl_xor_sync(0xffffffffu, s, o);
    if (lane == 0) red[8 + warp] = s;
    __syncthreads();
    if (tid == 0) {
        float tot = 0.f;
#pragma unroll
        for (int i = 0; i < 8; ++i) tot += red[8 + i];
        rmax[row] = bm;
        rinv[row] = 1.0f / tot;
    }
}

// ---------------------------------------------------------------------------
// ctx[n,h,k,v] = sum_s softmax_s(K)[k,s] * V[v,s]. One block per (n,h).
// Streams K/V in 32x128 chunks through smem (pitch 129 -> conflict-free).
// ---------------------------------------------------------------------------
__global__ void __launch_bounds__(256) ctx_kernel(
    const float* __restrict__ Kin,
    const float* __restrict__ Vin,
    const float* __restrict__ rmax,
    const float* __restrict__ rinv,
    float* __restrict__ ctx)
{
    const int nh = blockIdx.x;               // 0..127
    const int n = nh >> 3, h = nh & 7;
    const size_t base = ((size_t)n * CH + h * HC) * S;
    const float* Kp = Kin + base;
    const float* Vp = Vin + base;
    const int tid = threadIdx.x;

    __shared__ float sK[32][129];
    __shared__ float sV[32][129];
    __shared__ float smax[32], sinv[32];
    if (tid < 32) {
        smax[tid] = rmax[n * CH + h * HC + tid];
        sinv[tid] = rinv[n * CH + h * HC + tid];
    }

    float acc0 = 0.f, acc1 = 0.f, acc2 = 0.f, acc3 = 0.f;
    const int k  = tid >> 3;           // 0..31
    const int v0 = (tid & 7) * 4;      // 0,4,...,28

    for (int c = 0; c < S; c += 128) {
        __syncthreads();
#pragma unroll
        for (int e = 0; e < 16; ++e) {
            const int flat = tid + e * 256;
            const int r = flat >> 7, sc = flat & 127;
            sK[r][sc] = __expf(Kp[(size_t)r * S + c + sc] - smax[r]) * sinv[r];
            sV[r][sc] = Vp[(size_t)r * S + c + sc];
        }
        __syncthreads();
#pragma unroll 8
        for (int sIdx = 0; sIdx < 128; ++sIdx) {
            const float kv = sK[k][sIdx];
            acc0 = fmaf(kv, sV[v0 + 0][sIdx], acc0);
            acc1 = fmaf(kv, sV[v0 + 1][sIdx], acc1);
            acc2 = fmaf(kv, sV[v0 + 2][sIdx], acc2);
            acc3 = fmaf(kv, sV[v0 + 3][sIdx], acc3);
        }
    }
    float* cp = ctx + (size_t)nh * (HC * HC) + k * HC + v0;
    cp[0] = acc0; cp[1] = acc1; cp[2] = acc2; cp[3] = acc3;
}

// ---------------------------------------------------------------------------
// att[n, h*32+v, s] = sum_k softmax_k(Q)[k,s] * ctx[n,h,k,v].
// One thread per s-position; Q softmax over 32 channels done in registers.
// Grid: (S/256, NH, NB).
// ---------------------------------------------------------------------------
__global__ void __launch_bounds__(256) q_att(
    const float* __restrict__ Q,
    const float* __restrict__ ctx,
    float* __restrict__ att)
{
    const int n = blockIdx.z, h = blockIdx.y;
    const int s = blockIdx.x * 256 + threadIdx.x;

    __shared__ float sctx[HC][HC];
    const float* cp = ctx + (size_t)(n * NH + h) * (HC * HC);
    for (int i = threadIdx.x; i < HC * HC; i += 256)
        sctx[i >> 5][i & 31] = cp[i];
    __syncthreads();

    const float* qp = Q + ((size_t)n * CH + h * HC) * S + s;
    float q[HC];
    float m = -3.4e38f;
#pragma unroll
    for (int kk = 0; kk < HC; ++kk) {
        q[kk] = qp[(size_t)kk * S];
        m = fmaxf(m, q[kk]);
    }
    float ssum = 0.f;
#pragma unroll
    for (int kk = 0; kk < HC; ++kk) {
        q[kk] = __expf(q[kk] - m);
        ssum += q[kk];
    }
    const float inv = 1.0f / ssum;

    float* ap = att + ((size_t)n * CH + h * HC) * S + s;
#pragma unroll
    for (int vv = 0; vv < HC; ++vv) {
        float a = 0.f;
#pragma unroll
        for (int kk = 0; kk < HC; ++kk)
            a = fmaf(q[kk], sctx[kk][vv], a);
        ap[(size_t)vv * S] = a * inv;
    }
}

// ---------------------------------------------------------------------------
extern "C" void kernel_launch(void* const* d_in, const int* in_sizes, int n_in,
                              void* d_out, int out_size)
{
    const float* X  = (const float*)d_in[0];
    const float* Wk = (const float*)d_in[1];
    const float* bk = (const float*)d_in[2];
    const float* Wq = (const float*)d_in[3];
    const float* bq = (const float*)d_in[4];
    const float* Wv = (const float*)d_in[5];
    const float* bv = (const float*)d_in[6];
    const float* Wr = (const float*)d_in[7];
    const float* br = (const float*)d_in[8];
    float* out = (float*)d_out;

    void *pK, *pQ, *pV, *pA, *pC, *pM, *pI;
    cudaGetSymbolAddress(&pK, g_K);
    cudaGetSymbolAddress(&pQ, g_Q);
    cudaGetSymbolAddress(&pV, g_V);
    cudaGetSymbolAddress(&pA, g_att);
    cudaGetSymbolAddress(&pC, g_ctx);
    cudaGetSymbolAddress(&pM, g_rmax);
    cudaGetSymbolAddress(&pI, g_rinv);

    const dim3 gg(S / 128, CH / 128, NB);

    // 1) Q/K/V projections (1x1 conv == channel GEMM), bias fused
    sgemm_bias<<<gg, 256>>>(Wk, X, bk, nullptr, (float*)pK, CH, S, CH);
    sgemm_bias<<<gg, 256>>>(Wq, X, bq, nullptr, (float*)pQ, CH, S, CH);
    sgemm_bias<<<gg, 256>>>(Wv, X, bv, nullptr, (float*)pV, CH, S, CH);

    // 2) K softmax stats (over spatial dim)
    row_stats<<<NB * CH, 256>>>((const float*)pK, (float*)pM, (float*)pI);

    // 3) ctx = k_sm @ v^T per head
    ctx_kernel<<<NB * NH, 256>>>((const float*)pK, (const float*)pV,
                                 (const float*)pM, (const float*)pI, (float*)pC);

    // 4) Q softmax (over channels) fused with att = ctx^T @ q_sm
    q_att<<<dim3(S / 256, NH, NB), 256>>>((const float*)pQ, (const float*)pC,
                                          (float*)pA);

    // 5) output projection + bias + residual
    sgemm_bias<<<gg, 256>>>(Wr, (const float*)pA, br, X, out, CH, S, CH);
}

// round 2
// speedup vs baseline: 1.9770x; 1.9770x over previous
#include <cuda_runtime.h>
#include <math.h>

// Problem constants
static const int NB = 16;    // batch
static const int CH = 256;   // channels
static const int S  = 4096;  // spatial
static const int NH = 8;     // heads
static const int HC = 32;    // per-head channels

// ---------------- scratch (device globals; no allocations allowed) ----------
__device__ float g_K [(size_t)NB * CH * S];
__device__ float g_Q [(size_t)NB * CH * S];
__device__ float g_V [(size_t)NB * CH * S];
__device__ float g_att[(size_t)NB * CH * S];
__device__ float g_ctx[NB * NH * HC * HC];
__device__ float g_rmax[NB * CH];
__device__ float g_rinv[NB * CH];

// ---------------- tf32 mma helpers ------------------------------------------
static __device__ __forceinline__ unsigned f2tf(float x) {
    unsigned u;
    asm("cvt.rna.tf32.f32 %0, %1;" : "=r"(u) : "f"(x));
    return u;
}
static __device__ __forceinline__ void mma8(float d[4], const unsigned a[4],
                                            const unsigned b[2]) {
    asm volatile(
        "mma.sync.aligned.m16n8k8.row.col.f32.tf32.tf32.f32 "
        "{%0,%1,%2,%3}, {%4,%5,%6,%7}, {%8,%9}, {%0,%1,%2,%3};"
        : "+f"(d[0]), "+f"(d[1]), "+f"(d[2]), "+f"(d[3])
        : "r"(a[0]), "r"(a[1]), "r"(a[2]), "r"(a[3]), "r"(b[0]), "r"(b[1]));
}

// ---------------------------------------------------------------------------
// TF32 GEMM core: C[m][n0..n0+127] = A[256x256] * B[256 x N] (+bias)(+Res)
// Block 256 threads = 8 warps (4x2), warp tile 64x64, K-step 8, double buffer.
// Smem pitches: A pitch 264 (k-major), B pitch 136 -> conflict-free frag LDS.
// ---------------------------------------------------------------------------
#define PA 264
#define PB 136

__device__ __forceinline__ void gemm256_core(
    const float* __restrict__ A,     // [256][256] row-major weights
    const float* __restrict__ B,     // batch-offset, row k has stride N
    const float* __restrict__ bias,  // [256]
    const float* __restrict__ Res,   // batch-offset residual or nullptr
    float* __restrict__ C,           // batch-offset output
    int n0, int N)
{
    __shared__ unsigned sA[2][8 * PA];
    __shared__ unsigned sB[2][8 * PB];

    const int t = threadIdx.x;
    const int lane = t & 31, wid = t >> 5;
    const int g = lane >> 2, c = lane & 3;
    const int wm = (wid >> 1) * 64, wn = (wid & 1) * 64;

    const int brow = t >> 5, bcol = (t & 31) * 4;
    const float* Ap = A + (size_t)t * 256;
    const float* Bp = B + (size_t)brow * N + n0 + bcol;

    float acc[4][8][4];
#pragma unroll
    for (int i = 0; i < 4; ++i)
#pragma unroll
        for (int j = 0; j < 8; ++j)
#pragma unroll
            for (int r = 0; r < 4; ++r) acc[i][j][r] = 0.f;

    // prologue: fill stage 0
    {
        float4 x0 = *(const float4*)(Ap);
        float4 x1 = *(const float4*)(Ap + 4);
        unsigned* da = sA[0];
        da[0 * PA + t] = f2tf(x0.x); da[1 * PA + t] = f2tf(x0.y);
        da[2 * PA + t] = f2tf(x0.z); da[3 * PA + t] = f2tf(x0.w);
        da[4 * PA + t] = f2tf(x1.x); da[5 * PA + t] = f2tf(x1.y);
        da[6 * PA + t] = f2tf(x1.z); da[7 * PA + t] = f2tf(x1.w);
        float4 b4 = *(const float4*)(Bp);
        unsigned* db = sB[0] + brow * PB + bcol;
        db[0] = f2tf(b4.x); db[1] = f2tf(b4.y);
        db[2] = f2tf(b4.z); db[3] = f2tf(b4.w);
    }
    __syncthreads();

#pragma unroll 1
    for (int kt = 0; kt < 32; ++kt) {
        const int cur = kt & 1;
        float4 x0, x1, b4;
        if (kt < 31) {
            x0 = *(const float4*)(Ap + (kt + 1) * 8);
            x1 = *(const float4*)(Ap + (kt + 1) * 8 + 4);
            b4 = *(const float4*)(Bp + (size_t)(kt + 1) * 8 * N);
        }
        const unsigned* SA = sA[cur];
        const unsigned* SB = sB[cur];
        unsigned a[4][4], b[8][2];
#pragma unroll
        for (int mf = 0; mf < 4; ++mf) {
            const int m = wm + mf * 16 + g;
            a[mf][0] = SA[c * PA + m];
            a[mf][1] = SA[c * PA + m + 8];
            a[mf][2] = SA[(c + 4) * PA + m];
            a[mf][3] = SA[(c + 4) * PA + m + 8];
        }
#pragma unroll
        for (int nf = 0; nf < 8; ++nf) {
            const int n = wn + nf * 8 + g;
            b[nf][0] = SB[c * PB + n];
            b[nf][1] = SB[(c + 4) * PB + n];
        }
#pragma unroll
        for (int mf = 0; mf < 4; ++mf)
#pragma unroll
            for (int nf = 0; nf < 8; ++nf)
                mma8(acc[mf][nf], a[mf], b[nf]);
        if (kt < 31) {
            unsigned* da = sA[cur ^ 1];
            da[0 * PA + t] = f2tf(x0.x); da[1 * PA + t] = f2tf(x0.y);
            da[2 * PA + t] = f2tf(x0.z); da[3 * PA + t] = f2tf(x0.w);
            da[4 * PA + t] = f2tf(x1.x); da[5 * PA + t] = f2tf(x1.y);
            da[6 * PA + t] = f2tf(x1.z); da[7 * PA + t] = f2tf(x1.w);
            unsigned* db = sB[cur ^ 1] + brow * PB + bcol;
            db[0] = f2tf(b4.x); db[1] = f2tf(b4.y);
            db[2] = f2tf(b4.z); db[3] = f2tf(b4.w);
        }
        __syncthreads();
    }

    // epilogue
#pragma unroll
    for (int mf = 0; mf < 4; ++mf) {
        const int r0 = wm + mf * 16 + g;
        const int r1 = r0 + 8;
        const float bv0 = bias[r0];
        const float bv1 = bias[r1];
#pragma unroll
        for (int nf = 0; nf < 8; ++nf) {
            const int col = n0 + wn + nf * 8 + c * 2;
            const size_t o0 = (size_t)r0 * N + col;
            const size_t o1 = (size_t)r1 * N + col;
            float2 v0 = make_float2(acc[mf][nf][0] + bv0, acc[mf][nf][1] + bv0);
            float2 v1 = make_float2(acc[mf][nf][2] + bv1, acc[mf][nf][3] + bv1);
            if (Res) {
                float2 q0 = *(const float2*)(Res + o0);
                float2 q1 = *(const float2*)(Res + o1);
                v0.x += q0.x; v0.y += q0.y;
                v1.x += q1.x; v1.y += q1.y;
            }
            *(float2*)(C + o0) = v0;
            *(float2*)(C + o1) = v1;
        }
    }
}

// Fused QKV projection: blockIdx.y selects which weight/bias/output.
__global__ void __launch_bounds__(256) qkv_gemm(
    const float* __restrict__ X,
    const float* __restrict__ Wk, const float* __restrict__ bk,
    const float* __restrict__ Wq, const float* __restrict__ bq,
    const float* __restrict__ Wv, const float* __restrict__ bv,
    float* __restrict__ K, float* __restrict__ Q, float* __restrict__ V)
{
    const int z = blockIdx.z;
    const size_t zo = (size_t)z * CH * S;
    const float* A; const float* bias; float* C;
    if (blockIdx.y == 0)      { A = Wk; bias = bk; C = K + zo; }
    else if (blockIdx.y == 1) { A = Wq; bias = bq; C = Q + zo; }
    else                      { A = Wv; bias = bv; C = V + zo; }
    gemm256_core(A, X + zo, bias, nullptr, C, blockIdx.x * 128, S);
}

// Output projection + bias + residual.
__global__ void __launch_bounds__(256) out_gemm(
    const float* __restrict__ att, const float* __restrict__ Wr,
    const float* __restrict__ br, const float* __restrict__ X,
    float* __restrict__ out)
{
    const size_t zo = (size_t)blockIdx.z * CH * S;
    gemm256_core(Wr, att + zo, br, X + zo, out + zo, blockIdx.x * 128, S);
}

// ---------------------------------------------------------------------------
// Per-row softmax statistics for K (max, 1/sum(exp)) over S. One block/row.
// ---------------------------------------------------------------------------
__global__ void __launch_bounds__(256) row_stats(
    const float* __restrict__ Kin, float* __restrict__ rmax,
    float* __restrict__ rinv)
{
    const int row = blockIdx.x;
    const float* p = Kin + (size_t)row * S;
    const int tid = threadIdx.x;

    float v[16];
    float m = -3.4e38f;
#pragma unroll
    for (int e = 0; e < 16; ++e) {
        v[e] = p[tid + e * 256];
        m = fmaxf(m, v[e]);
    }
    __shared__ float red[16];
#pragma unroll
    for (int o = 16; o; o >>= 1) m = fmaxf(m, __shfl_xor_sync(0xffffffffu, m, o));
    const int warp = tid >> 5, lane = tid & 31;
    if (lane == 0) red[warp] = m;
    __syncthreads();
    float bm = red[0];
#pragma unroll
    for (int i = 1; i < 8; ++i) bm = fmaxf(bm, red[i]);

    float s = 0.f;
#pragma unroll
    for (int e = 0; e < 16; ++e) s += __expf(v[e] - bm);
#pragma unroll
    for (int o = 16; o; o >>= 1) s += __shfl_xor_sync(0xffffffffu, s, o);
    if (lane == 0) red[8 + warp] = s;
    __syncthreads();
    if (tid == 0) {
        float tot = 0.f;
#pragma unroll
        for (int i = 0; i < 8; ++i) tot += red[8 + i];
        rmax[row] = bm;
        rinv[row] = 1.0f / tot;
    }
}

// ---------------------------------------------------------------------------
// ctx[k][v] = sum_s softmax_s(K)[k,s] * V[v,s]  via TF32 mma.
// One block per (n,h); 8 warps split the s dimension; smem-tree reduce.
// ---------------------------------------------------------------------------
__global__ void __launch_bounds__(256) ctx_mma(
    const float* __restrict__ Kin, const float* __restrict__ Vin,
    const float* __restrict__ rmax, const float* __restrict__ rinv,
    float* __restrict__ ctx)
{
    __shared__ unsigned smem_u[8448];          // 33792 B, dual use
    unsigned* sK = smem_u;                     // [32][132]
    unsigned* sV = smem_u + 32 * 132;          // [32][132]
    __shared__ float ssmax[32], ssinv[32];

    const int nh = blockIdx.x;
    const size_t base = (size_t)nh * HC * S;
    const float* Kp = Kin + base;
    const float* Vp = Vin + base;
    const int t = threadIdx.x;
    const int lane = t & 31, wid = t >> 5;
    const int g = lane >> 2, c = lane & 3;

    if (t < 32) {
        ssmax[t] = rmax[nh * HC + t];
        ssinv[t] = rinv[nh * HC + t];
    }

    float acc[2][4][4];
#pragma unroll
    for (int i = 0; i < 2; ++i)
#pragma unroll
        for (int j = 0; j < 4; ++j)
#pragma unroll
            for (int r = 0; r < 4; ++r) acc[i][j][r] = 0.f;

    const int s_off = wid * 16;

    for (int c0 = 0; c0 < S; c0 += 128) {
        __syncthreads();
#pragma unroll
        for (int e = 0; e < 4; ++e) {
            const int f = t + e * 256;
            const int r = f >> 5;
            const int sc = (f & 31) * 4;
            float4 kv = *(const float4*)(Kp + (size_t)r * S + c0 + sc);
            const float mx = ssmax[r], iv = ssinv[r];
            uint4 ku;
            ku.x = f2tf(__expf(kv.x - mx) * iv);
            ku.y = f2tf(__expf(kv.y - mx) * iv);
            ku.z = f2tf(__expf(kv.z - mx) * iv);
            ku.w = f2tf(__expf(kv.w - mx) * iv);
            *(uint4*)(sK + r * 132 + sc) = ku;
            float4 vv = *(const float4*)(Vp + (size_t)r * S + c0 + sc);
            uint4 vu;
            vu.x = f2tf(vv.x); vu.y = f2tf(vv.y);
            vu.z = f2tf(vv.z); vu.w = f2tf(vv.w);
            *(uint4*)(sV + r * 132 + sc) = vu;
        }
        __syncthreads();
#pragma unroll
        for (int ks = 0; ks < 2; ++ks) {
            const int sc = s_off + ks * 8;
            unsigned a[2][4], b[4][2];
#pragma unroll
            for (int mf = 0; mf < 2; ++mf) {
                const int m = mf * 16 + g;
                a[mf][0] = sK[m * 132 + sc + c];
                a[mf][1] = sK[(m + 8) * 132 + sc + c];
                a[mf][2] = sK[m * 132 + sc + c + 4];
                a[mf][3] = sK[(m + 8) * 132 + sc + c + 4];
            }
#pragma unroll
            for (int nf = 0; nf < 4; ++nf) {
                const int v = nf * 8 + g;
                b[nf][0] = sV[v * 132 + sc + c];
                b[nf][1] = sV[v * 132 + sc + c + 4];
            }
#pragma unroll
            for (int mf = 0; mf < 2; ++mf)
#pragma unroll
                for (int nf = 0; nf < 4; ++nf)
                    mma8(acc[mf][nf], a[mf], b[nf]);
        }
    }

    // cross-warp reduction through smem
    __syncthreads();
    float* red = (float*)smem_u;  // [8][32][33]
#pragma unroll
    for (int mf = 0; mf < 2; ++mf)
#pragma unroll
        for (int nf = 0; nf < 4; ++nf) {
            const int m = mf * 16 + g;
            const int vcol = nf * 8 + c * 2;
            red[wid * 1056 + m * 33 + vcol]       = acc[mf][nf][0];
            red[wid * 1056 + m * 33 + vcol + 1]   = acc[mf][nf][1];
            red[wid * 1056 + (m + 8) * 33 + vcol]     = acc[mf][nf][2];
            red[wid * 1056 + (m + 8) * 33 + vcol + 1] = acc[mf][nf][3];
        }
    __syncthreads();
    float* cp = ctx + (size_t)nh * (HC * HC);
#pragma unroll
    for (int e = 0; e < 4; ++e) {
        const int o = t + e * 256;
        const int m = o >> 5, v = o & 31;
        float s = 0.f;
#pragma unroll
        for (int w = 0; w < 8; ++w) s += red[w * 1056 + m * 33 + v];
        cp[o] = s;
    }
}

// ---------------------------------------------------------------------------
// q_att: channel-softmax(Q) fused with att = ctx^T * q_sm via TF32 mma.
// One block per (n, h, 128-s-tile); 4 warps, each covers 32 s positions.
// ---------------------------------------------------------------------------
__global__ void __launch_bounds__(128) qatt_mma(
    const float* __restrict__ Q, const float* __restrict__ ctx,
    float* __restrict__ att)
{
    __shared__ unsigned sQ[32 * 136];
    __shared__ unsigned sT[32 * 36];

    const int n = blockIdx.z, h = blockIdx.y;
    const int s0 = blockIdx.x * 128;
    const int t = threadIdx.x;
    const int lane = t & 31, wid = t >> 5;
    const int g = lane >> 2, c = lane & 3;

    const float* Qp = Q + ((size_t)(n * NH + h)) * HC * S + s0;
    const float* cp = ctx + (size_t)(n * NH + h) * (HC * HC);

#pragma unroll
    for (int e = 0; e < 8; ++e) {
        const int f = t + e * 128;
        const int r = f >> 5;
        const int sc = (f & 31) * 4;
        float4 q4 = *(const float4*)(Qp + (size_t)r * S + sc);
        *(uint4*)(sQ + r * 136 + sc) = *(uint4*)&q4;   // raw f32 bits
    }
#pragma unroll
    for (int e = 0; e < 8; ++e) {
        const int o = t + e * 128;
        const int k = o >> 5, v = o & 31;
        sT[v * 36 + k] = f2tf(cp[o]);
    }
    __syncthreads();

    // softmax over k for this thread's s-column
    {
        float q[HC];
        float mx = -3.4e38f;
#pragma unroll
        for (int k = 0; k < HC; ++k) {
            q[k] = __uint_as_float(sQ[k * 136 + t]);
            mx = fmaxf(mx, q[k]);
        }
        float s = 0.f;
#pragma unroll
        for (int k = 0; k < HC; ++k) {
            q[k] = __expf(q[k] - mx);
            s += q[k];
        }
        const float inv = 1.0f / s;
#pragma unroll
        for (int k = 0; k < HC; ++k) sQ[k * 136 + t] = f2tf(q[k] * inv);
    }
    __syncthreads();

    // A frags (ctx^T), register-resident
    unsigned a[4][2][4];
#pragma unroll
    for (int k8 = 0; k8 < 4; ++k8)
#pragma unroll
        for (int mf = 0; mf < 2; ++mf) {
            const int v = mf * 16 + g;
            const int kk = k8 * 8 + c;
            a[k8][mf][0] = sT[v * 36 + kk];
            a[k8][mf][1] = sT[(v + 8) * 36 + kk];
            a[k8][mf][2] = sT[v * 36 + kk + 4];
            a[k8][mf][3] = sT[(v + 8) * 36 + kk + 4];
        }

    float acc[2][4][4];
#pragma unroll
    for (int i = 0; i < 2; ++i)
#pragma unroll
        for (int j = 0; j < 4; ++j)
#pragma unroll
            for (int r = 0; r < 4; ++r) acc[i][j][r] = 0.f;

    const int sw = wid * 32;
#pragma unroll
    for (int k8 = 0; k8 < 4; ++k8) {
        unsigned b[4][2];
#pragma unroll
        for (int nf = 0; nf < 4; ++nf) {
            const int s = sw + nf * 8 + g;
            const int kk = k8 * 8 + c;
            b[nf][0] = sQ[kk * 136 + s];
            b[nf][1] = sQ[(kk + 4) * 136 + s];
        }
#pragma unroll
        for (int mf = 0; mf < 2; ++mf)
#pragma unroll
            for (int nf = 0; nf < 4; ++nf)
                mma8(acc[mf][nf], a[k8][mf], b[nf]);
    }

    float* ap = att + ((size_t)(n * NH + h)) * HC * S + s0;
#pragma unroll
    for (int mf = 0; mf < 2; ++mf)
#pragma unroll
        for (int nf = 0; nf < 4; ++nf) {
            const int v0 = mf * 16 + g;
            const int scol = sw + nf * 8 + c * 2;
            *(float2*)(ap + (size_t)v0 * S + scol) =
                make_float2(acc[mf][nf][0], acc[mf][nf][1]);
            *(float2*)(ap + (size_t)(v0 + 8) * S + scol) =
                make_float2(acc[mf][nf][2], acc[mf][nf][3]);
        }
}

// ---------------------------------------------------------------------------
extern "C" void kernel_launch(void* const* d_in, const int* in_sizes, int n_in,
                              void* d_out, int out_size)
{
    const float* X  = (const float*)d_in[0];
    const float* Wk = (const float*)d_in[1];
    const float* bk = (const float*)d_in[2];
    const float* Wq = (const float*)d_in[3];
    const float* bq = (const float*)d_in[4];
    const float* Wv = (const float*)d_in[5];
    const float* bv = (const float*)d_in[6];
    const float* Wr = (const float*)d_in[7];
    const float* br = (const float*)d_in[8];
    float* out = (float*)d_out;

    void *pK, *pQ, *pV, *pA, *pC, *pM, *pI;
    cudaGetSymbolAddress(&pK, g_K);
    cudaGetSymbolAddress(&pQ, g_Q);
    cudaGetSymbolAddress(&pV, g_V);
    cudaGetSymbolAddress(&pA, g_att);
    cudaGetSymbolAddress(&pC, g_ctx);
    cudaGetSymbolAddress(&pM, g_rmax);
    cudaGetSymbolAddress(&pI, g_rinv);

    // 1) fused Q/K/V projections (TF32 tensor-core GEMM, bias fused)
    qkv_gemm<<<dim3(S / 128, 3, NB), 256>>>(X, Wk, bk, Wq, bq, Wv, bv,
                                            (float*)pK, (float*)pQ, (float*)pV);

    // 2) K softmax stats (over spatial dim)
    row_stats<<<NB * CH, 256>>>((const float*)pK, (float*)pM, (float*)pI);

    // 3) ctx = k_sm @ v^T per head (exp fused into operand load)
    ctx_mma<<<NB * NH, 256>>>((const float*)pK, (const float*)pV,
                              (const float*)pM, (const float*)pI, (float*)pC);

    // 4) Q channel-softmax fused with att = ctx^T @ q_sm
    qatt_mma<<<dim3(S / 128, NH, NB), 128>>>((const float*)pQ,
                                             (const float*)pC, (float*)pA);

    // 5) output projection + bias + residual
    out_gemm<<<dim3(S / 128, 1, NB), 256>>>((const float*)pA, Wr, br, X, out);
}

// round 3
// speedup vs baseline: 2.5465x; 1.2881x over previous
#include <cuda_runtime.h>
#include <math.h>

// Problem constants
static const int NB = 16;    // batch
static const int CH = 256;   // channels
static const int S  = 4096;  // spatial
static const int NH = 8;     // heads
static const int HC = 32;    // per-head channels
static const int CTXSPLIT = 4;

// ---------------- scratch (device globals; no allocations allowed) ----------
__device__ float g_K [(size_t)NB * CH * S];
__device__ float g_Q [(size_t)NB * CH * S];
__device__ float g_V [(size_t)NB * CH * S];
__device__ float g_att[(size_t)NB * CH * S];
__device__ float g_ctxp[CTXSPLIT * NB * NH * HC * HC];
__device__ float g_rmax[NB * CH];
__device__ float g_rinv[NB * CH];

// ---------------- tf32 mma helpers ------------------------------------------
static __device__ __forceinline__ unsigned f2tf(float x) {
    unsigned u;
    asm("cvt.rna.tf32.f32 %0, %1;" : "=r"(u) : "f"(x));
    return u;
}
static __device__ __forceinline__ void mma8(float d[4], const unsigned a[4],
                                            const unsigned b[2]) {
    asm volatile(
        "mma.sync.aligned.m16n8k8.row.col.f32.tf32.tf32.f32 "
        "{%0,%1,%2,%3}, {%4,%5,%6,%7}, {%8,%9}, {%0,%1,%2,%3};"
        : "+f"(d[0]), "+f"(d[1]), "+f"(d[2]), "+f"(d[3])
        : "r"(a[0]), "r"(a[1]), "r"(a[2]), "r"(a[3]), "r"(b[0]), "r"(b[1]));
}

// ---------------------------------------------------------------------------
// TF32 GEMM core: C[m0..m0+127][n0..n0+127] = A[256x256] * B[256 x N]
// (+bias)(+Res). 256 threads = 8 warps (2m x 4n), warp tile 64x32.
// k-step 16, double buffered, register-staged global loads.
// smem pitches: A 20 (m-major rows of 16 k), B 136 (k-major rows of 128 n).
// ---------------------------------------------------------------------------
#define GPA 20
#define GPB 136

__device__ __forceinline__ void gemm128_core(
    const float* __restrict__ A, int m0,
    const float* __restrict__ B,
    const float* __restrict__ bias,
    const float* __restrict__ Res,
    float* __restrict__ C,
    int n0, int N)
{
    __shared__ unsigned sA[2][128 * GPA];
    __shared__ unsigned sB[2][16 * GPB];

    const int t = threadIdx.x;
    const int lane = t & 31, wid = t >> 5;
    const int g = lane >> 2, c = lane & 3;
    const int wm = (wid >> 2) * 64, wn = (wid & 3) * 32;

    const int arow = t & 127, acol = (t >> 7) * 8;
    const int brow = t >> 4,  bcol = (t & 15) * 8;

    const float* Ap = A + (size_t)(m0 + arow) * 256 + acol;
    const float* Bp = B + (size_t)brow * N + n0 + bcol;

    float acc[4][4][4];
#pragma unroll
    for (int i = 0; i < 4; ++i)
#pragma unroll
        for (int j = 0; j < 4; ++j)
#pragma unroll
            for (int r = 0; r < 4; ++r) acc[i][j][r] = 0.f;

    float4 a0, a1, b0, b1;
    a0 = *(const float4*)(Ap);
    a1 = *(const float4*)(Ap + 4);
    b0 = *(const float4*)(Bp);
    b1 = *(const float4*)(Bp + 4);
    {
        uint4 u0 = make_uint4(f2tf(a0.x), f2tf(a0.y), f2tf(a0.z), f2tf(a0.w));
        uint4 u1 = make_uint4(f2tf(a1.x), f2tf(a1.y), f2tf(a1.z), f2tf(a1.w));
        *(uint4*)&sA[0][arow * GPA + acol]     = u0;
        *(uint4*)&sA[0][arow * GPA + acol + 4] = u1;
        uint4 v0 = make_uint4(f2tf(b0.x), f2tf(b0.y), f2tf(b0.z), f2tf(b0.w));
        uint4 v1 = make_uint4(f2tf(b1.x), f2tf(b1.y), f2tf(b1.z), f2tf(b1.w));
        *(uint4*)&sB[0][brow * GPB + bcol]     = v0;
        *(uint4*)&sB[0][brow * GPB + bcol + 4] = v1;
    }
    __syncthreads();

#pragma unroll 1
    for (int kt = 0; kt < 16; ++kt) {
        const int cur = kt & 1;
        if (kt < 15) {
            a0 = *(const float4*)(Ap + (kt + 1) * 16);
            a1 = *(const float4*)(Ap + (kt + 1) * 16 + 4);
            b0 = *(const float4*)(Bp + (size_t)(kt + 1) * 16 * N);
            b1 = *(const float4*)(Bp + (size_t)(kt + 1) * 16 * N + 4);
        }
        const unsigned* SA = sA[cur];
        const unsigned* SB = sB[cur];
#pragma unroll
        for (int ks = 0; ks < 2; ++ks) {
            const int kb = ks * 8;
            unsigned a[4][4], b[4][2];
#pragma unroll
            for (int mf = 0; mf < 4; ++mf) {
                const int m = wm + mf * 16 + g;
                a[mf][0] = SA[m * GPA + kb + c];
                a[mf][1] = SA[(m + 8) * GPA + kb + c];
                a[mf][2] = SA[m * GPA + kb + c + 4];
                a[mf][3] = SA[(m + 8) * GPA + kb + c + 4];
            }
#pragma unroll
            for (int nf = 0; nf < 4; ++nf) {
                const int n = wn + nf * 8 + g;
                b[nf][0] = SB[(kb + c) * GPB + n];
                b[nf][1] = SB[(kb + c + 4) * GPB + n];
            }
#pragma unroll
            for (int mf = 0; mf < 4; ++mf)
#pragma unroll
                for (int nf = 0; nf < 4; ++nf)
                    mma8(acc[mf][nf], a[mf], b[nf]);
        }
        if (kt < 15) {
            const int nxt = cur ^ 1;
            uint4 u0 = make_uint4(f2tf(a0.x), f2tf(a0.y), f2tf(a0.z), f2tf(a0.w));
            uint4 u1 = make_uint4(f2tf(a1.x), f2tf(a1.y), f2tf(a1.z), f2tf(a1.w));
            *(uint4*)&sA[nxt][arow * GPA + acol]     = u0;
            *(uint4*)&sA[nxt][arow * GPA + acol + 4] = u1;
            uint4 v0 = make_uint4(f2tf(b0.x), f2tf(b0.y), f2tf(b0.z), f2tf(b0.w));
            uint4 v1 = make_uint4(f2tf(b1.x), f2tf(b1.y), f2tf(b1.z), f2tf(b1.w));
            *(uint4*)&sB[nxt][brow * GPB + bcol]     = v0;
            *(uint4*)&sB[nxt][brow * GPB + bcol + 4] = v1;
        }
        __syncthreads();
    }

    // epilogue
#pragma unroll
    for (int mf = 0; mf < 4; ++mf) {
        const int r0 = m0 + wm + mf * 16 + g;
        const int r1 = r0 + 8;
        const float bv0 = bias[r0];
        const float bv1 = bias[r1];
#pragma unroll
        for (int nf = 0; nf < 4; ++nf) {
            const int col = n0 + wn + nf * 8 + c * 2;
            const size_t o0 = (size_t)r0 * N + col;
            const size_t o1 = (size_t)r1 * N + col;
            float2 v0 = make_float2(acc[mf][nf][0] + bv0, acc[mf][nf][1] + bv0);
            float2 v1 = make_float2(acc[mf][nf][2] + bv1, acc[mf][nf][3] + bv1);
            if (Res) {
                float2 q0 = *(const float2*)(Res + o0);
                float2 q1 = *(const float2*)(Res + o1);
                v0.x += q0.x; v0.y += q0.y;
                v1.x += q1.x; v1.y += q1.y;
            }
            *(float2*)(C + o0) = v0;
            *(float2*)(C + o1) = v1;
        }
    }
}

// Fused QKV projection: blockIdx.y = proj*2 + m-half.
__global__ void __launch_bounds__(256, 2) qkv_gemm(
    const float* __restrict__ X,
    const float* __restrict__ Wk, const float* __restrict__ bk,
    const float* __restrict__ Wq, const float* __restrict__ bq,
    const float* __restrict__ Wv, const float* __restrict__ bv,
    float* __restrict__ K, float* __restrict__ Q, float* __restrict__ V)
{
    const size_t zo = (size_t)blockIdx.z * CH * S;
    const int proj = blockIdx.y >> 1;
    const int m0 = (blockIdx.y & 1) * 128;
    const float* A; const float* bias; float* C;
    if (proj == 0)      { A = Wk; bias = bk; C = K + zo; }
    else if (proj == 1) { A = Wq; bias = bq; C = Q + zo; }
    else                { A = Wv; bias = bv; C = V + zo; }
    gemm128_core(A, m0, X + zo, bias, nullptr, C, blockIdx.x * 128, S);
}

// Output projection + bias + residual.
__global__ void __launch_bounds__(256, 2) out_gemm(
    const float* __restrict__ att, const float* __restrict__ Wr,
    const float* __restrict__ br, const float* __restrict__ X,
    float* __restrict__ out)
{
    const size_t zo = (size_t)blockIdx.z * CH * S;
    gemm128_core(Wr, blockIdx.y * 128, att + zo, br, X + zo, out + zo,
                 blockIdx.x * 128, S);
}

// ---------------------------------------------------------------------------
// Per-row softmax statistics for K (max, 1/sum(exp)) over S. One block/row.
// ---------------------------------------------------------------------------
__global__ void __launch_bounds__(256) row_stats(
    const float* __restrict__ Kin, float* __restrict__ rmax,
    float* __restrict__ rinv)
{
    const int row = blockIdx.x;
    const float* p = Kin + (size_t)row * S;
    const int tid = threadIdx.x;

    float v[16];
    float m = -3.4e38f;
#pragma unroll
    for (int e = 0; e < 16; ++e) {
        v[e] = p[tid + e * 256];
        m = fmaxf(m, v[e]);
    }
    __shared__ float red[16];
#pragma unroll
    for (int o = 16; o; o >>= 1) m = fmaxf(m, __shfl_xor_sync(0xffffffffu, m, o));
    const int warp = tid >> 5, lane = tid & 31;
    if (lane == 0) red[warp] = m;
    __syncthreads();
    float bm = red[0];
#pragma unroll
    for (int i = 1; i < 8; ++i) bm = fmaxf(bm, red[i]);

    float s = 0.f;
#pragma unroll
    for (int e = 0; e < 16; ++e) s += __expf(v[e] - bm);
#pragma unroll
    for (int o = 16; o; o >>= 1) s += __shfl_xor_sync(0xffffffffu, s, o);
    if (lane == 0) red[8 + warp] = s;
    __syncthreads();
    if (tid == 0) {
        float tot = 0.f;
#pragma unroll
        for (int i = 0; i < 8; ++i) tot += red[8 + i];
        rmax[row] = bm;
        rinv[row] = 1.0f / tot;
    }
}

// ---------------------------------------------------------------------------
// ctx partial: ctxp[y][nh][k][v] = sum_{s in quarter y} k_sm[k,s] * V[v,s].
// Grid (NB*NH, CTXSPLIT); 8 warps split s within each 128-chunk.
// ---------------------------------------------------------------------------
__global__ void __launch_bounds__(256) ctx_mma(
    const float* __restrict__ Kin, const float* __restrict__ Vin,
    const float* __restrict__ rmax, const float* __restrict__ rinv,
    float* __restrict__ ctxp)
{
    __shared__ unsigned smem_u[8448];          // dual use
    unsigned* sK = smem_u;                     // [32][132]
    unsigned* sV = smem_u + 32 * 132;          // [32][132]
    __shared__ float ssmax[32], ssinv[32];

    const int nh = blockIdx.x;
    const int q = blockIdx.y;
    const size_t base = (size_t)nh * HC * S;
    const float* Kp = Kin + base;
    const float* Vp = Vin + base;
    const int t = threadIdx.x;
    const int lane = t & 31, wid = t >> 5;
    const int g = lane >> 2, c = lane & 3;

    if (t < 32) {
        ssmax[t] = rmax[nh * HC + t];
        ssinv[t] = rinv[nh * HC + t];
    }

    float acc[2][4][4];
#pragma unroll
    for (int i = 0; i < 2; ++i)
#pragma unroll
        for (int j = 0; j < 4; ++j)
#pragma unroll
            for (int r = 0; r < 4; ++r) acc[i][j][r] = 0.f;

    const int s_off = wid * 16;
    const int c_beg = q * (S / CTXSPLIT);
    const int c_end = c_beg + (S / CTXSPLIT);

    for (int c0 = c_beg; c0 < c_end; c0 += 128) {
        __syncthreads();
#pragma unroll
        for (int e = 0; e < 4; ++e) {
            const int f = t + e * 256;
            const int r = f >> 5;
            const int sc = (f & 31) * 4;
            float4 kv = *(const float4*)(Kp + (size_t)r * S + c0 + sc);
            const float mx = ssmax[r], iv = ssinv[r];
            uint4 ku;
            ku.x = f2tf(__expf(kv.x - mx) * iv);
            ku.y = f2tf(__expf(kv.y - mx) * iv);
            ku.z = f2tf(__expf(kv.z - mx) * iv);
            ku.w = f2tf(__expf(kv.w - mx) * iv);
            *(uint4*)(sK + r * 132 + sc) = ku;
            float4 vv = *(const float4*)(Vp + (size_t)r * S + c0 + sc);
            uint4 vu;
            vu.x = f2tf(vv.x); vu.y = f2tf(vv.y);
            vu.z = f2tf(vv.z); vu.w = f2tf(vv.w);
            *(uint4*)(sV + r * 132 + sc) = vu;
        }
        __syncthreads();
#pragma unroll
        for (int ks = 0; ks < 2; ++ks) {
            const int sc = s_off + ks * 8;
            unsigned a[2][4], b[4][2];
#pragma unroll
            for (int mf = 0; mf < 2; ++mf) {
                const int m = mf * 16 + g;
                a[mf][0] = sK[m * 132 + sc + c];
                a[mf][1] = sK[(m + 8) * 132 + sc + c];
                a[mf][2] = sK[m * 132 + sc + c + 4];
                a[mf][3] = sK[(m + 8) * 132 + sc + c + 4];
            }
#pragma unroll
            for (int nf = 0; nf < 4; ++nf) {
                const int v = nf * 8 + g;
                b[nf][0] = sV[v * 132 + sc + c];
                b[nf][1] = sV[v * 132 + sc + c + 4];
            }
#pragma unroll
            for (int mf = 0; mf < 2; ++mf)
#pragma unroll
                for (int nf = 0; nf < 4; ++nf)
                    mma8(acc[mf][nf], a[mf], b[nf]);
        }
    }

    // cross-warp reduction through smem
    __syncthreads();
    float* red = (float*)smem_u;  // [8][32][33]
#pragma unroll
    for (int mf = 0; mf < 2; ++mf)
#pragma unroll
        for (int nf = 0; nf < 4; ++nf) {
            const int m = mf * 16 + g;
            const int vcol = nf * 8 + c * 2;
            red[wid * 1056 + m * 33 + vcol]           = acc[mf][nf][0];
            red[wid * 1056 + m * 33 + vcol + 1]       = acc[mf][nf][1];
            red[wid * 1056 + (m + 8) * 33 + vcol]     = acc[mf][nf][2];
            red[wid * 1056 + (m + 8) * 33 + vcol + 1] = acc[mf][nf][3];
        }
    __syncthreads();
    float* cp = ctxp + (size_t)q * (NB * NH * HC * HC) + (size_t)nh * (HC * HC);
#pragma unroll
    for (int e = 0; e < 4; ++e) {
        const int o = t + e * 256;
        const int m = o >> 5, v = o & 31;
        float s = 0.f;
#pragma unroll
        for (int w = 0; w < 8; ++w) s += red[w * 1056 + m * 33 + v];
        cp[o] = s;
    }
}

// ---------------------------------------------------------------------------
// q_att: channel-softmax(Q) fused with att = ctx^T * q_sm via TF32 mma.
// One block per (n, h, 128-s-tile); 4 warps, each covers 32 s positions.
// ---------------------------------------------------------------------------
__global__ void __launch_bounds__(128) qatt_mma(
    const float* __restrict__ Q, const float* __restrict__ ctxp,
    float* __restrict__ att)
{
    __shared__ unsigned sQ[32 * 136];
    __shared__ unsigned sT[32 * 36];

    const int n = blockIdx.z, h = blockIdx.y;
    const int s0 = blockIdx.x * 128;
    const int t = threadIdx.x;
    const int lane = t & 31, wid = t >> 5;
    const int g = lane >> 2, c = lane & 3;

    const float* Qp = Q + ((size_t)(n * NH + h)) * HC * S + s0;
    const float* cp = ctxp + (size_t)(n * NH + h) * (HC * HC);
    const size_t coff = (size_t)NB * NH * HC * HC;

#pragma unroll
    for (int e = 0; e < 8; ++e) {
        const int f = t + e * 128;
        const int r = f >> 5;
        const int sc = (f & 31) * 4;
        float4 q4 = *(const float4*)(Qp + (size_t)r * S + sc);
        *(uint4*)(sQ + r * 136 + sc) = *(uint4*)&q4;   // raw f32 bits
    }
#pragma unroll
    for (int e = 0; e < 8; ++e) {
        const int o = t + e * 128;
        const int k = o >> 5, v = o & 31;
        float s = cp[o] + cp[o + coff] + cp[o + 2 * coff] + cp[o + 3 * coff];
        sT[v * 36 + k] = f2tf(s);
    }
    __syncthreads();

    // softmax over k for this thread's s-column
    {
        float q[HC];
        float mx = -3.4e38f;
#pragma unroll
        for (int k = 0; k < HC; ++k) {
            q[k] = __uint_as_float(sQ[k * 136 + t]);
            mx = fmaxf(mx, q[k]);
        }
        float s = 0.f;
#pragma unroll
        for (int k = 0; k < HC; ++k) {
            q[k] = __expf(q[k] - mx);
            s += q[k];
        }
        const float inv = 1.0f / s;
#pragma unroll
        for (int k = 0; k < HC; ++k) sQ[k * 136 + t] = f2tf(q[k] * inv);
    }
    __syncthreads();

    // A frags (ctx^T), register-resident
    unsigned a[4][2][4];
#pragma unroll
    for (int k8 = 0; k8 < 4; ++k8)
#pragma unroll
        for (int mf = 0; mf < 2; ++mf) {
            const int v = mf * 16 + g;
            const int kk = k8 * 8 + c;
            a[k8][mf][0] = sT[v * 36 + kk];
            a[k8][mf][1] = sT[(v + 8) * 36 + kk];
            a[k8][mf][2] = sT[v * 36 + kk + 4];
            a[k8][mf][3] = sT[(v + 8) * 36 + kk + 4];
        }

    float acc[2][4][4];
#pragma unroll
    for (int i = 0; i < 2; ++i)
#pragma unroll
        for (int j = 0; j < 4; ++j)
#pragma unroll
            for (int r = 0; r < 4; ++r) acc[i][j][r] = 0.f;

    const int sw = wid * 32;
#pragma unroll
    for (int k8 = 0; k8 < 4; ++k8) {
        unsigned b[4][2];
#pragma unroll
        for (int nf = 0; nf < 4; ++nf) {
            const int s = sw + nf * 8 + g;
            const int kk = k8 * 8 + c;
            b[nf][0] = sQ[kk * 136 + s];
            b[nf][1] = sQ[(kk + 4) * 136 + s];
        }
#pragma unroll
        for (int mf = 0; mf < 2; ++mf)
#pragma unroll
            for (int nf = 0; nf < 4; ++nf)
                mma8(acc[mf][nf], a[k8][mf], b[nf]);
    }

    float* ap = att + ((size_t)(n * NH + h)) * HC * S + s0;
#pragma unroll
    for (int mf = 0; mf < 2; ++mf)
#pragma unroll
        for (int nf = 0; nf < 4; ++nf) {
            const int v0 = mf * 16 + g;
            const int scol = sw + nf * 8 + c * 2;
            *(float2*)(ap + (size_t)v0 * S + scol) =
                make_float2(acc[mf][nf][0], acc[mf][nf][1]);
            *(float2*)(ap + (size_t)(v0 + 8) * S + scol) =
                make_float2(acc[mf][nf][2], acc[mf][nf][3]);
        }
}

// ---------------------------------------------------------------------------
extern "C" void kernel_launch(void* const* d_in, const int* in_sizes, int n_in,
                              void* d_out, int out_size)
{
    const float* X  = (const float*)d_in[0];
    const float* Wk = (const float*)d_in[1];
    const float* bk = (const float*)d_in[2];
    const float* Wq = (const float*)d_in[3];
    const float* bq = (const float*)d_in[4];
    const float* Wv = (const float*)d_in[5];
    const float* bv = (const float*)d_in[6];
    const float* Wr = (const float*)d_in[7];
    const float* br = (const float*)d_in[8];
    float* out = (float*)d_out;

    void *pK, *pQ, *pV, *pA, *pC, *pM, *pI;
    cudaGetSymbolAddress(&pK, g_K);
    cudaGetSymbolAddress(&pQ, g_Q);
    cudaGetSymbolAddress(&pV, g_V);
    cudaGetSymbolAddress(&pA, g_att);
    cudaGetSymbolAddress(&pC, g_ctxp);
    cudaGetSymbolAddress(&pM, g_rmax);
    cudaGetSymbolAddress(&pI, g_rinv);

    // 1) fused Q/K/V projections
    qkv_gemm<<<dim3(S / 128, 6, NB), 256>>>(X, Wk, bk, Wq, bq, Wv, bv,
                                            (float*)pK, (float*)pQ, (float*)pV);

    // 2) K softmax stats (over spatial dim)
    row_stats<<<NB * CH, 256>>>((const float*)pK, (float*)pM, (float*)pI);

    // 3) ctx partials = k_sm @ v^T per head, split over s
    ctx_mma<<<dim3(NB * NH, CTXSPLIT), 256>>>((const float*)pK, (const float*)pV,
                                              (const float*)pM, (const float*)pI,
                                              (float*)pC);

    // 4) Q channel-softmax fused with att = ctx^T @ q_sm (sums ctx partials)
    qatt_mma<<<dim3(S / 128, NH, NB), 128>>>((const float*)pQ,
                                             (const float*)pC, (float*)pA);

    // 5) output projection + bias + residual
    out_gemm<<<dim3(S / 128, 2, NB), 256>>>((const float*)pA, Wr, br, X, out);
}

// round 5
// speedup vs baseline: 3.2400x; 1.2724x over previous
#include <cuda_runtime.h>
#include <cuda_bf16.h>
#include <math.h>

// Problem constants
static const int NB = 16;    // batch
static const int CH = 256;   // channels
static const int S  = 4096;  // spatial
static const int NH = 8;     // heads
static const int HC = 32;    // per-head channels
static const int CTXSPLIT = 4;

typedef __nv_bfloat16 bf16;

// ---------------- scratch (device globals; no allocations allowed) ----------
__device__ bf16  g_K [(size_t)NB * CH * S];
__device__ bf16  g_Q [(size_t)NB * CH * S];
__device__ bf16  g_V [(size_t)NB * CH * S];
__device__ bf16  g_att[(size_t)NB * CH * S];
__device__ float g_ctxp[CTXSPLIT * NB * NH * HC * HC];
__device__ float g_rmax[NB * CH];
__device__ float g_rinv[NB * CH];

// ---------------- helpers ----------------------------------------------------
static __device__ __forceinline__ unsigned pack2(float a, float b) {
    __nv_bfloat162 h = __floats2bfloat162_rn(a, b);
    return *reinterpret_cast<unsigned*>(&h);
}
static __device__ __forceinline__ float2 unpack2(unsigned u) {
    return __bfloat1622float2(*reinterpret_cast<__nv_bfloat162*>(&u));
}
static __device__ __forceinline__ void mma16(float d[4], const unsigned a[4],
                                             const unsigned b[2]) {
    asm volatile(
        "mma.sync.aligned.m16n8k16.row.col.f32.bf16.bf16.f32 "
        "{%0,%1,%2,%3}, {%4,%5,%6,%7}, {%8,%9}, {%0,%1,%2,%3};"
        : "+f"(d[0]), "+f"(d[1]), "+f"(d[2]), "+f"(d[3])
        : "r"(a[0]), "r"(a[1]), "r"(a[2]), "r"(a[3]), "r"(b[0]), "r"(b[1]));
}

// ---------------------------------------------------------------------------
// BF16 GEMM core: C[m0..+127][n0..+127] = A(fp32 W)[256x256] * B[256 x N]
// 256 threads = 8 warps (2m x 4n), warp tile 64x32, k-step 16, double buffer.
// smem layout: k-pair-major, A pitch 132 (b32), B pitch 136 (b32).
// BSRC_BF16: B source dtype. OUT_BF16: output dtype (else fp32 + residual).
// ---------------------------------------------------------------------------
#define PAB 132
#define PBB 136

template<bool BSRC_BF16, bool OUT_BF16>
__device__ __forceinline__ void gemm_core(
    const float* __restrict__ A, int m0,
    const void* __restrict__ Bsrc,
    const float* __restrict__ bias,
    const float* __restrict__ Res,
    void* __restrict__ Cout,
    int n0, int N)
{
    __shared__ __align__(16) unsigned sA[2][8 * PAB];
    __shared__ __align__(16) unsigned sB[2][8 * PBB];

    const int t = threadIdx.x;
    const int lane = t & 31, wid = t >> 5;
    const int g = lane >> 2, c = lane & 3;
    const int wm = (wid >> 2) * 64, wn = (wid & 3) * 32;

    const int arow = t & 127;
    const int acol8 = (t >> 7) * 8;      // 0 or 8
    const int kp = t >> 5;               // 0..7
    const int bcol = (t & 31) * 4;

    const float* Ap = A + (size_t)(m0 + arow) * 256 + acol8;
    const float* Bp32 = BSRC_BF16 ? nullptr
        : (const float*)Bsrc + (size_t)(2 * kp) * N + n0 + bcol;
    const bf16* Bp16 = BSRC_BF16
        ? (const bf16*)Bsrc + (size_t)(2 * kp) * N + n0 + bcol : nullptr;

    float acc[4][4][4];
#pragma unroll
    for (int i = 0; i < 4; ++i)
#pragma unroll
        for (int j = 0; j < 4; ++j)
#pragma unroll
            for (int r = 0; r < 4; ++r) acc[i][j][r] = 0.f;

    float4 a0, a1, r0, r1;
    uint2 h0, h1;

    // prologue: load + store stage 0
    a0 = *(const float4*)(Ap);
    a1 = *(const float4*)(Ap + 4);
    if (BSRC_BF16) { h0 = *(const uint2*)(Bp16); h1 = *(const uint2*)(Bp16 + N); }
    else           { r0 = *(const float4*)(Bp32); r1 = *(const float4*)(Bp32 + N); }
    {
        const int cb = acol8 >> 1;
        sA[0][(cb + 0) * PAB + arow] = pack2(a0.x, a0.y);
        sA[0][(cb + 1) * PAB + arow] = pack2(a0.z, a0.w);
        sA[0][(cb + 2) * PAB + arow] = pack2(a1.x, a1.y);
        sA[0][(cb + 3) * PAB + arow] = pack2(a1.z, a1.w);
        uint4 u;
        if (BSRC_BF16) {
            u.x = __byte_perm(h0.x, h1.x, 0x5410);
            u.y = __byte_perm(h0.x, h1.x, 0x7632);
            u.z = __byte_perm(h0.y, h1.y, 0x5410);
            u.w = __byte_perm(h0.y, h1.y, 0x7632);
        } else {
            u.x = pack2(r0.x, r1.x); u.y = pack2(r0.y, r1.y);
            u.z = pack2(r0.z, r1.z); u.w = pack2(r0.w, r1.w);
        }
        *(uint4*)&sB[0][kp * PBB + bcol] = u;
    }
    __syncthreads();

#pragma unroll 1
    for (int kt = 0; kt < 16; ++kt) {
        const int cur = kt & 1;
        if (kt < 15) {
            a0 = *(const float4*)(Ap + (kt + 1) * 16);
            a1 = *(const float4*)(Ap + (kt + 1) * 16 + 4);
            if (BSRC_BF16) {
                h0 = *(const uint2*)(Bp16 + (size_t)(kt + 1) * 16 * N);
                h1 = *(const uint2*)(Bp16 + (size_t)(kt + 1) * 16 * N + N);
            } else {
                r0 = *(const float4*)(Bp32 + (size_t)(kt + 1) * 16 * N);
                r1 = *(const float4*)(Bp32 + (size_t)(kt + 1) * 16 * N + N);
            }
        }
        const unsigned* SA = sA[cur];
        const unsigned* SB = sB[cur];
        unsigned a[4][4], b[4][2];
#pragma unroll
        for (int mf = 0; mf < 4; ++mf) {
            const int m = wm + mf * 16 + g;
            a[mf][0] = SA[c * PAB + m];
            a[mf][1] = SA[c * PAB + m + 8];
            a[mf][2] = SA[(4 + c) * PAB + m];
            a[mf][3] = SA[(4 + c) * PAB + m + 8];
        }
#pragma unroll
        for (int nf = 0; nf < 4; ++nf) {
            const int n = wn + nf * 8 + g;
            b[nf][0] = SB[c * PBB + n];
            b[nf][1] = SB[(4 + c) * PBB + n];
        }
#pragma unroll
        for (int mf = 0; mf < 4; ++mf)
#pragma unroll
            for (int nf = 0; nf < 4; ++nf)
                mma16(acc[mf][nf], a[mf], b[nf]);
        if (kt < 15) {
            const int nxt = cur ^ 1;
            const int cb = acol8 >> 1;
            sA[nxt][(cb + 0) * PAB + arow] = pack2(a0.x, a0.y);
            sA[nxt][(cb + 1) * PAB + arow] = pack2(a0.z, a0.w);
            sA[nxt][(cb + 2) * PAB + arow] = pack2(a1.x, a1.y);
            sA[nxt][(cb + 3) * PAB + arow] = pack2(a1.z, a1.w);
            uint4 u;
            if (BSRC_BF16) {
                u.x = __byte_perm(h0.x, h1.x, 0x5410);
                u.y = __byte_perm(h0.x, h1.x, 0x7632);
                u.z = __byte_perm(h0.y, h1.y, 0x5410);
                u.w = __byte_perm(h0.y, h1.y, 0x7632);
            } else {
                u.x = pack2(r0.x, r1.x); u.y = pack2(r0.y, r1.y);
                u.z = pack2(r0.z, r1.z); u.w = pack2(r0.w, r1.w);
            }
            *(uint4*)&sB[nxt][kp * PBB + bcol] = u;
        }
        __syncthreads();
    }

    // epilogue
#pragma unroll
    for (int mf = 0; mf < 4; ++mf) {
        const int row0 = m0 + wm + mf * 16 + g;
        const int row1 = row0 + 8;
        const float bv0 = bias[row0];
        const float bv1 = bias[row1];
#pragma unroll
        for (int nf = 0; nf < 4; ++nf) {
            const int col = n0 + wn + nf * 8 + c * 2;
            const size_t o0 = (size_t)row0 * N + col;
            const size_t o1 = (size_t)row1 * N + col;
            if (OUT_BF16) {
                bf16* C = (bf16*)Cout;
                *(unsigned*)(C + o0) = pack2(acc[mf][nf][0] + bv0,
                                             acc[mf][nf][1] + bv0);
                *(unsigned*)(C + o1) = pack2(acc[mf][nf][2] + bv1,
                                             acc[mf][nf][3] + bv1);
            } else {
                float* C = (float*)Cout;
                float2 q0 = *(const float2*)(Res + o0);
                float2 q1 = *(const float2*)(Res + o1);
                *(float2*)(C + o0) = make_float2(acc[mf][nf][0] + bv0 + q0.x,
                                                 acc[mf][nf][1] + bv0 + q0.y);
                *(float2*)(C + o1) = make_float2(acc[mf][nf][2] + bv1 + q1.x,
                                                 acc[mf][nf][3] + bv1 + q1.y);
            }
        }
    }
}

// Fused QKV projection: blockIdx.y = proj*2 + m-half.
__global__ void __launch_bounds__(256, 2) qkv_gemm(
    const float* __restrict__ X,
    const float* __restrict__ Wk, const float* __restrict__ bk,
    const float* __restrict__ Wq, const float* __restrict__ bq,
    const float* __restrict__ Wv, const float* __restrict__ bv,
    bf16* __restrict__ K, bf16* __restrict__ Q, bf16* __restrict__ V)
{
    const size_t zo = (size_t)blockIdx.z * CH * S;
    const int proj = blockIdx.y >> 1;
    const int m0 = (blockIdx.y & 1) * 128;
    const float* A; const float* bias; bf16* C;
    if (proj == 0)      { A = Wk; bias = bk; C = K + zo; }
    else if (proj == 1) { A = Wq; bias = bq; C = Q + zo; }
    else                { A = Wv; bias = bv; C = V + zo; }
    gemm_core<false, true>(A, m0, X + zo, bias, nullptr, C, blockIdx.x * 128, S);
}

// Output projection + bias + residual (fp32 out).
__global__ void __launch_bounds__(256, 2) out_gemm(
    const bf16* __restrict__ att, const float* __restrict__ Wr,
    const float* __restrict__ br, const float* __restrict__ X,
    float* __restrict__ out)
{
    const size_t zo = (size_t)blockIdx.z * CH * S;
    gemm_core<true, false>(Wr, blockIdx.y * 128, att + zo, br, X + zo,
                           out + zo, blockIdx.x * 128, S);
}

// ---------------------------------------------------------------------------
// Per-row softmax statistics for K (max, 1/sum(exp)) over S. One block/row.
// ---------------------------------------------------------------------------
__global__ void __launch_bounds__(256) row_stats(
    const bf16* __restrict__ Kin, float* __restrict__ rmax,
    float* __restrict__ rinv)
{
    const int row = blockIdx.x;
    const bf16* p = Kin + (size_t)row * S;
    const int tid = threadIdx.x;

    uint4 u0 = *(const uint4*)(p + tid * 16);
    uint4 u1 = *(const uint4*)(p + tid * 16 + 8);
    float v[16];
    {
        float2 f;
        f = unpack2(u0.x); v[0] = f.x; v[1] = f.y;
        f = unpack2(u0.y); v[2] = f.x; v[3] = f.y;
        f = unpack2(u0.z); v[4] = f.x; v[5] = f.y;
        f = unpack2(u0.w); v[6] = f.x; v[7] = f.y;
        f = unpack2(u1.x); v[8] = f.x; v[9] = f.y;
        f = unpack2(u1.y); v[10] = f.x; v[11] = f.y;
        f = unpack2(u1.z); v[12] = f.x; v[13] = f.y;
        f = unpack2(u1.w); v[14] = f.x; v[15] = f.y;
    }
    float m = -3.4e38f;
#pragma unroll
    for (int e = 0; e < 16; ++e) m = fmaxf(m, v[e]);
    __shared__ float red[16];
#pragma unroll
    for (int o = 16; o; o >>= 1) m = fmaxf(m, __shfl_xor_sync(0xffffffffu, m, o));
    const int warp = tid >> 5, lane = tid & 31;
    if (lane == 0) red[warp] = m;
    __syncthreads();
    float bm = red[0];
#pragma unroll
    for (int i = 1; i < 8; ++i) bm = fmaxf(bm, red[i]);

    float s = 0.f;
#pragma unroll
    for (int e = 0; e < 16; ++e) s += __expf(v[e] - bm);
#pragma unroll
    for (int o = 16; o; o >>= 1) s += __shfl_xor_sync(0xffffffffu, s, o);
    if (lane == 0) red[8 + warp] = s;
    __syncthreads();
    if (tid == 0) {
        float tot = 0.f;
#pragma unroll
        for (int i = 0; i < 8; ++i) tot += red[8 + i];
        rmax[row] = bm;
        rinv[row] = 1.0f / tot;
    }
}

// ---------------------------------------------------------------------------
// ctx partial: ctxp[y][nh][k][v] = sum_{s in quarter y} k_sm[k,s] * V[v,s].
// bf16 mma, contraction over s (pairs along s). Grid (NB*NH, CTXSPLIT).
// ---------------------------------------------------------------------------
#define PCX 68

__global__ void __launch_bounds__(256) ctx_mma(
    const bf16* __restrict__ Kin, const bf16* __restrict__ Vin,
    const float* __restrict__ rmax, const float* __restrict__ rinv,
    float* __restrict__ ctxp)
{
    __shared__ __align__(16) unsigned smem_u[8448];  // dual use
    unsigned* sK = smem_u;                 // [32][PCX]
    unsigned* sV = smem_u + 32 * PCX;      // [32][PCX]
    __shared__ float ssmax[32], ssinv[32];

    const int nh = blockIdx.x;
    const int q = blockIdx.y;
    const size_t base = (size_t)nh * HC * S;
    const bf16* Kp = Kin + base;
    const bf16* Vp = Vin + base;
    const int t = threadIdx.x;
    const int lane = t & 31, wid = t >> 5;
    const int g = lane >> 2, c = lane & 3;

    if (t < 32) {
        ssmax[t] = rmax[nh * HC + t];
        ssinv[t] = rinv[nh * HC + t];
    }

    float acc[2][4][4];
#pragma unroll
    for (int i = 0; i < 2; ++i)
#pragma unroll
        for (int j = 0; j < 4; ++j)
#pragma unroll
            for (int r = 0; r < 4; ++r) acc[i][j][r] = 0.f;

    const int spBase = wid * 8;
    const int c_beg = q * (S / CTXSPLIT);
    const int c_end = c_beg + (S / CTXSPLIT);

    for (int c0 = c_beg; c0 < c_end; c0 += 128) {
        __syncthreads();
#pragma unroll
        for (int e = 0; e < 2; ++e) {
            const int f = t + e * 256;
            const int r = f >> 4;
            const int so8 = (f & 15) * 8;
            uint4 ku = *(const uint4*)(Kp + (size_t)r * S + c0 + so8);
            const float mx = ssmax[r], iv = ssinv[r];
            float2 k0 = unpack2(ku.x), k1 = unpack2(ku.y);
            float2 k2 = unpack2(ku.z), k3 = unpack2(ku.w);
            uint4 ou;
            ou.x = pack2(__expf(k0.x - mx) * iv, __expf(k0.y - mx) * iv);
            ou.y = pack2(__expf(k1.x - mx) * iv, __expf(k1.y - mx) * iv);
            ou.z = pack2(__expf(k2.x - mx) * iv, __expf(k2.y - mx) * iv);
            ou.w = pack2(__expf(k3.x - mx) * iv, __expf(k3.y - mx) * iv);
            *(uint4*)(sK + r * PCX + (f & 15) * 4) = ou;
            // V pairs are already (s even, s odd) packed in source order
            *(uint4*)(sV + r * PCX + (f & 15) * 4) =
                *(const uint4*)(Vp + (size_t)r * S + c0 + so8);
        }
        __syncthreads();
        unsigned a[2][4], b[4][2];
#pragma unroll
        for (int mf = 0; mf < 2; ++mf) {
            const int m = mf * 16 + g;
            a[mf][0] = sK[m * PCX + spBase + c];
            a[mf][1] = sK[(m + 8) * PCX + spBase + c];
            a[mf][2] = sK[m * PCX + spBase + 4 + c];
            a[mf][3] = sK[(m + 8) * PCX + spBase + 4 + c];
        }
#pragma unroll
        for (int nf = 0; nf < 4; ++nf) {
            const int v = nf * 8 + g;
            b[nf][0] = sV[v * PCX + spBase + c];
            b[nf][1] = sV[v * PCX + spBase + 4 + c];
        }
#pragma unroll
        for (int mf = 0; mf < 2; ++mf)
#pragma unroll
            for (int nf = 0; nf < 4; ++nf)
                mma16(acc[mf][nf], a[mf], b[nf]);
    }

    // cross-warp reduction through smem
    __syncthreads();
    float* red = (float*)smem_u;  // [8][32][33]
#pragma unroll
    for (int mf = 0; mf < 2; ++mf)
#pragma unroll
        for (int nf = 0; nf < 4; ++nf) {
            const int m = mf * 16 + g;
            const int vcol = nf * 8 + c * 2;
            red[wid * 1056 + m * 33 + vcol]           = acc[mf][nf][0];
            red[wid * 1056 + m * 33 + vcol + 1]       = acc[mf][nf][1];
            red[wid * 1056 + (m + 8) * 33 + vcol]     = acc[mf][nf][2];
            red[wid * 1056 + (m + 8) * 33 + vcol + 1] = acc[mf][nf][3];
        }
    __syncthreads();
    float* cp = ctxp + (size_t)q * (NB * NH * HC * HC) + (size_t)nh * (HC * HC);
#pragma unroll
    for (int e = 0; e < 4; ++e) {
        const int o = t + e * 256;
        const int m = o >> 5, v = o & 31;
        float s = 0.f;
#pragma unroll
        for (int w = 0; w < 8; ++w) s += red[w * 1056 + m * 33 + v];
        cp[o] = s;
    }
}

// ---------------------------------------------------------------------------
// q_att: channel-softmax(Q) fused with att = ctx^T * q_sm via bf16 mma.
// One block per (n, h, 128-s tile); 4 warps x 32 s each. Contraction = 32 ch.
// ---------------------------------------------------------------------------
#define PQ 132
#define PT 20

__global__ void __launch_bounds__(128) qatt_mma(
    const bf16* __restrict__ Q, const float* __restrict__ ctxp,
    bf16* __restrict__ att)
{
    __shared__ __align__(16) unsigned sQ[16 * PQ];   // [k-pair][s]
    __shared__ __align__(16) unsigned sT[32 * PT];   // [v][k-pair]

    const int n = blockIdx.z, h = blockIdx.y;
    const int s0 = blockIdx.x * 128;
    const int t = threadIdx.x;
    const int lane = t & 31, wid = t >> 5;
    const int g = lane >> 2, c = lane & 3;

    const bf16* Qp = Q + ((size_t)(n * NH + h)) * HC * S + s0;
    const float* cp = ctxp + (size_t)(n * NH + h) * (HC * HC);
    const size_t coff = (size_t)NB * NH * HC * HC;

    // fill sQ: pairs along channel k
#pragma unroll
    for (int e = 0; e < 2; ++e) {
        const int i = t + e * 128;
        const int kp = i >> 4;
        const int so8 = (i & 15) * 8;
        uint2 q0a = *(const uint2*)(Qp + (size_t)(2 * kp) * S + so8);
        uint2 q0b = *(const uint2*)(Qp + (size_t)(2 * kp) * S + so8 + 4);
        uint2 q1a = *(const uint2*)(Qp + (size_t)(2 * kp + 1) * S + so8);
        uint2 q1b = *(const uint2*)(Qp + (size_t)(2 * kp + 1) * S + so8 + 4);
        uint4 u0, u1;
        u0.x = __byte_perm(q0a.x, q1a.x, 0x5410);
        u0.y = __byte_perm(q0a.x, q1a.x, 0x7632);
        u0.z = __byte_perm(q0a.y, q1a.y, 0x5410);
        u0.w = __byte_perm(q0a.y, q1a.y, 0x7632);
        u1.x = __byte_perm(q0b.x, q1b.x, 0x5410);
        u1.y = __byte_perm(q0b.x, q1b.x, 0x7632);
        u1.z = __byte_perm(q0b.y, q1b.y, 0x5410);
        u1.w = __byte_perm(q0b.y, q1b.y, 0x7632);
        *(uint4*)(sQ + kp * PQ + so8) = u0;
        *(uint4*)(sQ + kp * PQ + so8 + 4) = u1;
    }
    // fill sT: ctx^T (sum of 4 partials), pairs along k
#pragma unroll
    for (int e = 0; e < 4; ++e) {
        const int o = t + e * 128;
        const int kp = o >> 5, v = o & 31;
        const int i0 = (2 * kp) * 32 + v;
        const int i1 = i0 + 32;
        float v0 = cp[i0] + cp[i0 + coff] + cp[i0 + 2 * coff] + cp[i0 + 3 * coff];
        float v1 = cp[i1] + cp[i1 + coff] + cp[i1 + 2 * coff] + cp[i1 + 3 * coff];
        sT[v * PT + kp] = pack2(v0, v1);
    }
    __syncthreads();

    // softmax over 32 channels for this thread's s-column (fp32)
    {
        float q[HC];
#pragma unroll
        for (int kp = 0; kp < 16; ++kp) {
            float2 f = unpack2(sQ[kp * PQ + t]);
            q[2 * kp] = f.x; q[2 * kp + 1] = f.y;
        }
        float mx = -3.4e38f;
#pragma unroll
        for (int k = 0; k < HC; ++k) mx = fmaxf(mx, q[k]);
        float s = 0.f;
#pragma unroll
        for (int k = 0; k < HC; ++k) { q[k] = __expf(q[k] - mx); s += q[k]; }
        const float inv = 1.0f / s;
#pragma unroll
        for (int kp = 0; kp < 16; ++kp)
            sQ[kp * PQ + t] = pack2(q[2 * kp] * inv, q[2 * kp + 1] * inv);
    }
    __syncthreads();

    // A frags (ctx^T), register-resident: 2 k16 steps x 2 m-frags
    unsigned a[2][2][4];
#pragma unroll
    for (int ks = 0; ks < 2; ++ks)
#pragma unroll
        for (int mf = 0; mf < 2; ++mf) {
            const int v = mf * 16 + g;
            a[ks][mf][0] = sT[v * PT + ks * 8 + c];
            a[ks][mf][1] = sT[(v + 8) * PT + ks * 8 + c];
            a[ks][mf][2] = sT[v * PT + ks * 8 + 4 + c];
            a[ks][mf][3] = sT[(v + 8) * PT + ks * 8 + 4 + c];
        }

    float acc[2][4][4];
#pragma unroll
    for (int i = 0; i < 2; ++i)
#pragma unroll
        for (int j = 0; j < 4; ++j)
#pragma unroll
            for (int r = 0; r < 4; ++r) acc[i][j][r] = 0.f;

    const int sw = wid * 32;
#pragma unroll
    for (int ks = 0; ks < 2; ++ks) {
        unsigned b[4][2];
#pragma unroll
        for (int nf = 0; nf < 4; ++nf) {
            const int s = sw + nf * 8 + g;
            b[nf][0] = sQ[(ks * 8 + c) * PQ + s];
            b[nf][1] = sQ[(ks * 8 + 4 + c) * PQ + s];
        }
#pragma unroll
        for (int mf = 0; mf < 2; ++mf)
#pragma unroll
            for (int nf = 0; nf < 4; ++nf)
                mma16(acc[mf][nf], a[ks][mf], b[nf]);
    }

    bf16* ap = att + ((size_t)(n * NH + h)) * HC * S + s0;
#pragma unroll
    for (int mf = 0; mf < 2; ++mf)
#pragma unroll
        for (int nf = 0; nf < 4; ++nf) {
            const int v0 = mf * 16 + g;
            const int scol = sw + nf * 8 + c * 2;
            *(unsigned*)(ap + (size_t)v0 * S + scol) =
                pack2(acc[mf][nf][0], acc[mf][nf][1]);
            *(unsigned*)(ap + (size_t)(v0 + 8) * S + scol) =
                pack2(acc[mf][nf][2], acc[mf][nf][3]);
        }
}

// ---------------------------------------------------------------------------
extern "C" void kernel_launch(void* const* d_in, const int* in_sizes, int n_in,
                              void* d_out, int out_size)
{
    const float* X  = (const float*)d_in[0];
    const float* Wk = (const float*)d_in[1];
    const float* bk = (const float*)d_in[2];
    const float* Wq = (const float*)d_in[3];
    const float* bq = (const float*)d_in[4];
    const float* Wv = (const float*)d_in[5];
    const float* bv = (const float*)d_in[6];
    const float* Wr = (const float*)d_in[7];
    const float* br = (const float*)d_in[8];
    float* out = (float*)d_out;

    void *pK, *pQ, *pV, *pA, *pC, *pM, *pI;
    cudaGetSymbolAddress(&pK, g_K);
    cudaGetSymbolAddress(&pQ, g_Q);
    cudaGetSymbolAddress(&pV, g_V);
    cudaGetSymbolAddress(&pA, g_att);
    cudaGetSymbolAddress(&pC, g_ctxp);
    cudaGetSymbolAddress(&pM, g_rmax);
    cudaGetSymbolAddress(&pI, g_rinv);

    // 1) fused Q/K/V projections (bf16 mma, bf16 outputs)
    qkv_gemm<<<dim3(S / 128, 6, NB), 256>>>(X, Wk, bk, Wq, bq, Wv, bv,
                                            (bf16*)pK, (bf16*)pQ, (bf16*)pV);

    // 2) K softmax stats (over spatial dim)
    row_stats<<<NB * CH, 256>>>((const bf16*)pK, (float*)pM, (float*)pI);

    // 3) ctx partials = k_sm @ v^T per head, split over s
    ctx_mma<<<dim3(NB * NH, CTXSPLIT), 256>>>((const bf16*)pK, (const bf16*)pV,
                                              (const float*)pM, (const float*)pI,
                                              (float*)pC);

    // 4) Q channel-softmax fused with att = ctx^T @ q_sm (sums ctx partials)
    qatt_mma<<<dim3(S / 128, NH, NB), 128>>>((const bf16*)pQ,
                                             (const float*)pC, (bf16*)pA);

    // 5) output projection + bias + residual (fp32 out)
    out_gemm<<<dim3(S / 128, 2, NB), 256>>>((const bf16*)pA, Wr, br, X, out);
}